// round 2
// baseline (speedup 1.0000x reference)
#include <cuda_runtime.h>
#include <cuda_bf16.h>
#include <stdint.h>

#define BZ 4
#define LL 1024
#define SS 8
#define KH 128
#define EE 512
#define PRIME 2147483647u
#define EMPTYV 0xffffffffu

// ---------------- device scratch ----------------
__device__ __align__(16) unsigned int  g_sig[2 * BZ * LL * KH];    // [row][k]
__device__ __align__(16) unsigned int  g_sigT[2 * BZ * KH * LL];   // [(qk,b)][k][l]
__device__ __align__(16) int           g_cnti[BZ * LL * LL];       // match counts (int) 16MB
__device__ float         g_lut[129];
__device__ int           g_is64;
__device__ __align__(16) float         g_WvT[EE * EE];
__device__ __align__(16) float         g_Mpart[4 * EE * EE];       // split-K partials
__device__ __align__(16) __nv_bfloat16 g_Mbt[EE * EE];             // M2^T bf16 [e1][e2]
__device__ __align__(16) __nv_bfloat16 g_vbt[BZ * EE * LL];        // value^T bf16 [b][e1][r]
__device__ __align__(16) __nv_bfloat16 g_ubf[BZ * LL * EE];        // u bf16 [b][r][e2]
__device__ __align__(16) float         g_vsum[BZ * EE];
__device__ __align__(16) float         g_tvec[BZ * EE];
__device__ __align__(16) float         g_usum[BZ * EE];            // exact fp32 colsum of u
__device__ __align__(16) float         g_cvec[EE];
__device__ float         g_rowinv[BZ * LL];
__device__ int           g_nzc[BZ * LL];
__device__ __align__(16) int           g_nzi[BZ * LL * LL];
__device__ __align__(16) float         g_nzw[BZ * LL * LL];

// ---------------- init: dtype detection + score LUT ----------------
__global__ void init_kernel(const void* ha) {
    int t = threadIdx.x;
    if (t == 0) {
        const int* p = (const int*)ha;
        int is64 = 1;
        for (int i = 0; i < 16; i++)
            if (p[2 * i + 1] != 0) is64 = 0;
        g_is64 = is64;
    }
    if (t < 129) {
        float j = (float)t / 128.0f;
        float delta = 16.0f * (1.0f - j) / (1.0f + j);
        float s = expf(-0.3f * delta);
        g_lut[t] = expf(s);
    }
}

// ---------------- MinHash sketches ----------------
__global__ __launch_bounds__(128) void sketch_kernel(const void* tsq, const void* tsk,
                                                     const void* ha, const void* hb) {
    __shared__ long long ids[SS];
    int row = blockIdx.x;
    int k = threadIdx.x;
    int is64 = g_is64;
    const void* ts = (row < BZ * LL) ? tsq : tsk;
    int r = row & (BZ * LL - 1);
    if (k < SS) {
        ids[k] = is64 ? ((const long long*)ts)[r * SS + k]
                      : (long long)((const int*)ts)[r * SS + k];
    }
    __syncthreads();

    unsigned int mn = 0xffffffffu;
    if (is64) {
        unsigned long long a = (unsigned long long)((const long long*)ha)[k];
        unsigned long long b = (unsigned long long)((const long long*)hb)[k];
        #pragma unroll
        for (int s = 0; s < SS; s++) {
            unsigned long long x = (unsigned long long)ids[s] * a + b;
            unsigned long long t = (x >> 31) + (x & 0x7fffffffULL);
            t = (t >> 31) + (t & 0x7fffffffULL);
            if (t >= 0x7fffffffULL) t -= 0x7fffffffULL;
            unsigned int v = (unsigned int)t;
            if (v < mn) mn = v;
        }
    } else {
        unsigned int a = (unsigned int)((const int*)ha)[k];
        unsigned int b = (unsigned int)((const int*)hb)[k];
        #pragma unroll
        for (int s = 0; s < SS; s++) {
            unsigned int xu = (unsigned int)((long long)ids[s]) * a + b;
            int x = (int)xu;
            long long m = (long long)x % (long long)PRIME;
            if (m < 0) m += (long long)PRIME;
            unsigned int v = (unsigned int)m;
            if (v < mn) mn = v;
        }
    }
    g_sig[row * KH + k] = mn;
}

// ---------------- transpose signatures: [z*1024+l][k] -> [z][k][l], z = qk*4+b ----
__global__ void sigT_kernel() {
    __shared__ unsigned int t[32][33];
    int z = blockIdx.z;
    int x0 = blockIdx.x * 32, y0 = blockIdx.y * 32;   // x=k, y=l
    int tx = threadIdx.x, ty = threadIdx.y;
    #pragma unroll
    for (int i = 0; i < 32; i += 8)
        t[ty + i][tx] = g_sig[(z * LL + y0 + ty + i) * KH + x0 + tx];
    __syncthreads();
    #pragma unroll
    for (int i = 0; i < 32; i += 8)
        g_sigT[(z * KH + x0 + ty + i) * LL + y0 + tx] = t[tx][ty + i];
}

// ---------------- transpose Wv -> WvT ----------------
__global__ void transpose_kernel(const float* __restrict__ in) {
    __shared__ float t[32][33];
    int bx = blockIdx.x, by = blockIdx.y;
    int tx = threadIdx.x, ty = threadIdx.y;
    #pragma unroll
    for (int i = 0; i < 32; i += 8)
        t[ty + i][tx] = in[(by * 32 + ty + i) * EE + bx * 32 + tx];
    __syncthreads();
    #pragma unroll
    for (int i = 0; i < 32; i += 8)
        g_WvT[(bx * 32 + ty + i) * EE + by * 32 + tx] = t[tx][ty + i];
}

// ---------------- M2^T split-K GEMM: D[e1][e2] = sum_o WvT[e1][o]*Wo[e2][o] ------
// BM=BN=64, BK=16, splitK=4, 256 threads, 4x4 per thread
__global__ __launch_bounds__(256) void gemm_M2_kernel(const float* __restrict__ Wo) {
    __shared__ float As[16][68];
    __shared__ float Bs[16][68];
    int tid = threadIdx.x;
    int mi = tid & 15, ni = tid >> 4;
    int i0 = blockIdx.x * 64, j0 = blockIdx.y * 64;
    int kz = blockIdx.z;
    float acc[4][4] = {};
    for (int k0 = kz * 128; k0 < kz * 128 + 128; k0 += 16) {
        {
            int ar = tid >> 2, ac = tid & 3;
            float4 v = *(const float4*)&g_WvT[(i0 + ar) * EE + k0 + ac * 4];
            As[ac * 4 + 0][ar] = v.x; As[ac * 4 + 1][ar] = v.y;
            As[ac * 4 + 2][ar] = v.z; As[ac * 4 + 3][ar] = v.w;
            float4 w = *(const float4*)&Wo[(j0 + ar) * EE + k0 + ac * 4];
            Bs[ac * 4 + 0][ar] = w.x; Bs[ac * 4 + 1][ar] = w.y;
            Bs[ac * 4 + 2][ar] = w.z; Bs[ac * 4 + 3][ar] = w.w;
        }
        __syncthreads();
        #pragma unroll
        for (int k = 0; k < 16; k++) {
            float4 a4 = *(float4*)&As[k][mi * 4];
            float4 b4 = *(float4*)&Bs[k][ni * 4];
            float a[4] = {a4.x, a4.y, a4.z, a4.w};
            float bb[4] = {b4.x, b4.y, b4.z, b4.w};
            #pragma unroll
            for (int r = 0; r < 4; r++)
                #pragma unroll
                for (int c = 0; c < 4; c++)
                    acc[r][c] += a[r] * bb[c];
        }
        __syncthreads();
    }
    float* outp = g_Mpart + (size_t)kz * EE * EE;
    #pragma unroll
    for (int r = 0; r < 4; r++) {
        float4 o = make_float4(acc[r][0], acc[r][1], acc[r][2], acc[r][3]);
        *(float4*)&outp[(i0 + mi * 4 + r) * EE + j0 + ni * 4] = o;
    }
}

__global__ void reduceM_kernel() {
    int idx = blockIdx.x * 256 + threadIdx.x;   // 0 .. 262143
    float s = g_Mpart[idx] + g_Mpart[idx + EE * EE]
            + g_Mpart[idx + 2 * EE * EE] + g_Mpart[idx + 3 * EE * EE];
    g_Mbt[idx] = __float2bfloat16_rn(s);
}

// ---------------- value -> transposed bf16 [b][e1][r] ----------------
__global__ void convT_kernel(const float* __restrict__ value) {
    __shared__ float t[32][33];
    int b = blockIdx.z;
    int e0 = blockIdx.x * 32, r0 = blockIdx.y * 32;
    int tx = threadIdx.x, ty = threadIdx.y;
    #pragma unroll
    for (int i = 0; i < 32; i += 8)
        t[ty + i][tx] = value[((size_t)b * LL + r0 + ty + i) * EE + e0 + tx];
    __syncthreads();
    #pragma unroll
    for (int i = 0; i < 32; i += 8)
        g_vbt[((size_t)b * EE + e0 + ty + i) * LL + r0 + tx] = __float2bfloat16_rn(t[tx][ty + i]);
}

// ---------------- exact dense-term path: vsum, t = Wv@vsum, usum = Wo@t ---------
__global__ void vsum_kernel(const float* __restrict__ value) {
    int b = blockIdx.y;
    int e = blockIdx.x * 128 + threadIdx.x;
    const float* vp = value + (size_t)b * LL * EE + e;
    float acc = 0.f;
    for (int r = 0; r < LL; r++) acc += vp[(size_t)r * EE];
    g_vsum[b * EE + e] = acc;
}
__global__ void tvec_kernel(const float* __restrict__ Wv) {
    int b = blockIdx.y;
    int o = blockIdx.x * 128 + threadIdx.x;
    float acc = 0.f;
    const float* wr = Wv + (size_t)o * EE;
    const float* vs = g_vsum + b * EE;
    for (int e = 0; e < EE; e++) acc += wr[e] * vs[e];
    g_tvec[b * EE + o] = acc;
}
__global__ void usum_kernel(const float* __restrict__ Wo) {
    int b = blockIdx.y;
    int e2 = blockIdx.x * 128 + threadIdx.x;
    float acc = 0.f;
    const float* wr = Wo + (size_t)e2 * EE;
    const float* tv = g_tvec + b * EE;
    for (int o = 0; o < EE; o++) acc += wr[o] * tv[o];
    g_usum[b * EE + e2] = acc;
}
__global__ void cvec_kernel(const float* __restrict__ Wo,
                            const float* __restrict__ bv,
                            const float* __restrict__ bo) {
    int e2 = blockIdx.x * 128 + threadIdx.x;
    float acc = bo[e2];
    for (int e = 0; e < EE; e++) acc += Wo[(size_t)e2 * EE + e] * bv[e];
    g_cvec[e2] = acc;
}

// ---------------- u GEMM (bf16 HFMA2): u[r][e2] = sum_e1 vbt[e1][r]*Mbt[e1][e2] -
// BM=128, BN=64, BK=16, 256 threads, 8x4 per thread (acc packed as 8 x 2 bf16x2)
__global__ __launch_bounds__(256) void gemm_u_kernel() {
    __shared__ __nv_bfloat16 As[16][128];
    __shared__ __nv_bfloat16 Bs[16][64];
    int tid = threadIdx.x;
    int mi = tid & 15, ni = tid >> 4;       // mi: 16 row groups of 8, ni: 16 col groups of 4
    int rt = blockIdx.x;                    // 0..31 global row tile
    int b  = rt >> 3;
    int i0 = (rt & 7) * 128;
    int j0 = blockIdx.y * 64;
    const __nv_bfloat16* vb = g_vbt + (size_t)b * EE * LL;

    __nv_bfloat162 acc[8][2];
    __nv_bfloat162 z2 = __float2bfloat162_rn(0.f);
    #pragma unroll
    for (int r = 0; r < 8; r++) { acc[r][0] = z2; acc[r][1] = z2; }

    for (int k0 = 0; k0 < EE; k0 += 16) {
        {   // A: 16k x 128r bf16 = 256 uint4; one per thread
            int kk = tid >> 4, seg = tid & 15;
            *(uint4*)&As[kk][seg * 8] =
                *(const uint4*)(vb + (size_t)(k0 + kk) * LL + i0 + seg * 8);
        }
        if (tid < 128) {  // B: 16k x 64c = 128 uint4
            int kk = tid >> 3, seg = tid & 7;
            *(uint4*)&Bs[kk][seg * 8] =
                *(const uint4*)(g_Mbt + (size_t)(k0 + kk) * EE + j0 + seg * 8);
        }
        __syncthreads();
        #pragma unroll
        for (int kk = 0; kk < 16; kk++) {
            uint4 a4 = *(uint4*)&As[kk][mi * 8];
            uint2 b2 = *(uint2*)&Bs[kk][ni * 4];
            __nv_bfloat162 bb0 = *(__nv_bfloat162*)&b2.x;
            __nv_bfloat162 bb1 = *(__nv_bfloat162*)&b2.y;
            unsigned ua[4] = {a4.x, a4.y, a4.z, a4.w};
            #pragma unroll
            for (int p = 0; p < 4; p++) {
                __nv_bfloat162 ap = *(__nv_bfloat162*)&ua[p];
                __nv_bfloat162 al = __low2bfloat162(ap);
                __nv_bfloat162 ah = __high2bfloat162(ap);
                acc[2 * p][0]     = __hfma2(al, bb0, acc[2 * p][0]);
                acc[2 * p][1]     = __hfma2(al, bb1, acc[2 * p][1]);
                acc[2 * p + 1][0] = __hfma2(ah, bb0, acc[2 * p + 1][0]);
                acc[2 * p + 1][1] = __hfma2(ah, bb1, acc[2 * p + 1][1]);
            }
        }
        __syncthreads();
    }
    #pragma unroll
    for (int r = 0; r < 8; r++) {
        uint2 o;
        o.x = *(unsigned*)&acc[r][0];
        o.y = *(unsigned*)&acc[r][1];
        size_t row = (size_t)b * LL + i0 + mi * 8 + r;
        *(uint2*)(g_ubf + row * EE + j0 + ni * 4) = o;
    }
}

// ---------------- zero the count matrix ----------------
__global__ void zero_kernel() {
    int idx = blockIdx.x * 256 + threadIdx.x;   // 0 .. 1M-1 (int4 units)
    ((int4*)g_cnti)[idx] = make_int4(0, 0, 0, 0);
}

// ---------------- hash join: per (slot k, batch b) ----------------
__global__ __launch_bounds__(256) void hashjoin_kernel() {
    __shared__ unsigned int tval[2048];
    __shared__ int          trow[2048];
    int k = blockIdx.x, b = blockIdx.y;
    int tid = threadIdx.x;
    for (int i = tid; i < 2048; i += 256) tval[i] = EMPTYV;
    __syncthreads();

    const unsigned* SK = g_sigT + ((size_t)((1 * BZ + b) * KH + k)) * LL;
    const unsigned* SQ = g_sigT + ((size_t)((0 * BZ + b) * KH + k)) * LL;

    // insert keys
    for (int j = tid; j < LL; j += 256) {
        unsigned v = SK[j];
        int slot = (int)((v * 2654435761u) >> 20) & 2047;
        while (true) {
            unsigned old = atomicCAS(&tval[slot], EMPTYV, v);
            if (old == EMPTYV) { trow[slot] = j; break; }
            slot = (slot + 1) & 2047;
        }
    }
    __syncthreads();

    // probe queries
    int* cb = g_cnti + (size_t)b * LL * LL;
    for (int i = tid; i < LL; i += 256) {
        unsigned v = SQ[i];
        int slot = (int)((v * 2654435761u) >> 20) & 2047;
        while (tval[slot] != EMPTYV) {
            if (tval[slot] == v)
                atomicAdd(&cb[(size_t)i * LL + trow[slot]], 1);
            slot = (slot + 1) & 2047;
        }
    }
}

// ---------------- per-row sparse list + softmax denom (warp per row) ----------
__global__ __launch_bounds__(256) void build_sparse_kernel() {
    int row = blockIdx.x * 8 + (threadIdx.x >> 5);
    int lane = threadIdx.x & 31;
    const int* cr = g_cnti + (size_t)row * LL;
    float lut0 = g_lut[0];
    float rsum = 0.f;
    int base = 0;
    int* oi = g_nzi + (size_t)row * LL;
    float* ow = g_nzw + (size_t)row * LL;
    for (int c = 0; c < 32; c++) {
        int j = c * 32 + lane;
        int m = cr[j];
        rsum += g_lut[m];
        unsigned mask = __ballot_sync(0xffffffffu, m != 0);
        if (m) {
            int pos = base + __popc(mask & ((1u << lane) - 1u));
            oi[pos] = j;
            ow[pos] = g_lut[m] - lut0;
        }
        base += __popc(mask);
    }
    #pragma unroll
    for (int o = 16; o; o >>= 1) rsum += __shfl_xor_sync(0xffffffffu, rsum, o);
    if (lane == 0) {
        g_nzc[row] = base;
        g_rowinv[row] = 1.0f / rsum;
    }
}

// ---------------- output ----------------
__global__ __launch_bounds__(128) void out_kernel(float* __restrict__ out) {
    int row = blockIdx.x;
    int b = row >> 10;
    int e4 = threadIdx.x;              // handles 4 e2 (one float4 of output)
    float lut0 = g_lut[0];
    float4 us = ((const float4*)g_usum)[b * 128 + e4];
    float4 acc = make_float4(us.x * lut0, us.y * lut0, us.z * lut0, us.w * lut0);
    int n = g_nzc[row];
    const int* oi = g_nzi + (size_t)row * LL;
    const float* ow = g_nzw + (size_t)row * LL;
    const uint2* ub = (const uint2*)g_ubf + (size_t)b * LL * 128;
    for (int t = 0; t < n; t++) {
        int j = oi[t];
        float w = ow[t];
        uint2 u2 = ub[(size_t)j * 128 + e4];
        float2 lo = __bfloat1622float2(*(__nv_bfloat162*)&u2.x);
        float2 hi = __bfloat1622float2(*(__nv_bfloat162*)&u2.y);
        acc.x += w * lo.x; acc.y += w * lo.y;
        acc.z += w * hi.x; acc.w += w * hi.y;
    }
    float inv = g_rowinv[row];
    float4 cc = ((const float4*)g_cvec)[e4];
    float4 o = make_float4(acc.x * inv + cc.x, acc.y * inv + cc.y,
                           acc.z * inv + cc.z, acc.w * inv + cc.w);
    ((float4*)out)[(size_t)row * 128 + e4] = o;
}

// ---------------- launch ----------------
extern "C" void kernel_launch(void* const* d_in, const int* in_sizes, int n_in,
                              void* d_out, int out_size) {
    const float* value = (const float*)d_in[2];
    const void*  tsq   = d_in[3];
    const void*  tsk   = d_in[4];
    const void*  ha    = d_in[5];
    const void*  hb    = d_in[6];
    const float* Wv    = (const float*)d_in[11];
    const float* bv    = (const float*)d_in[12];
    const float* Wo    = (const float*)d_in[13];
    const float* bo    = (const float*)d_in[14];
    float* out = (float*)d_out;

    init_kernel<<<1, 160>>>(ha);
    sketch_kernel<<<2 * BZ * LL, 128>>>(tsq, tsk, ha, hb);
    sigT_kernel<<<dim3(KH / 32, LL / 32, 2 * BZ), dim3(32, 8)>>>();
    transpose_kernel<<<dim3(16, 16), dim3(32, 8)>>>(Wv);
    gemm_M2_kernel<<<dim3(8, 8, 4), 256>>>(Wo);
    reduceM_kernel<<<EE * EE / 256, 256>>>();
    convT_kernel<<<dim3(EE / 32, LL / 32, BZ), dim3(32, 8)>>>(value);
    vsum_kernel<<<dim3(EE / 128, BZ), 128>>>(value);
    tvec_kernel<<<dim3(EE / 128, BZ), 128>>>(Wv);
    usum_kernel<<<dim3(EE / 128, BZ), 128>>>(Wo);
    cvec_kernel<<<EE / 128, 128>>>(Wo, bv, bo);
    zero_kernel<<<BZ * LL * LL / 4 / 256, 256>>>();
    hashjoin_kernel<<<dim3(KH, BZ), 256>>>();
    build_sparse_kernel<<<BZ * LL / 8, 256>>>();
    out_kernel<<<BZ * LL, 128>>>(out);
}